// round 1
// baseline (speedup 1.0000x reference)
#include <cuda_runtime.h>
#include <math.h>

#define BB   8
#define HH   96
#define WW   160
#define HW   (HH*WW)

// scratch (allocation-free rule: __device__ globals)
__device__ float g_h1[8*256*96*160];
__device__ float g_h2[8*256*96*160];
__device__ float g_u1[8*128*96*160];

// ---------------------------------------------------------------------------
// 3x3 conv (pad 1) + optional BN + ReLU.  IC multiple of 8. OC multiple of 32.
// Block: 256 threads -> tile 32 OC x 8 H x 32 W. Thread: 4 OC x 8 W.
// ---------------------------------------------------------------------------
__global__ __launch_bounds__(256) void conv3x3_bn_relu(
    const float* __restrict__ in, const float* __restrict__ wgt,
    const float* __restrict__ bias,
    const float* __restrict__ gam, const float* __restrict__ bet,
    const float* __restrict__ mu,  const float* __restrict__ var,
    float* __restrict__ out, int IC, int OC, int useBN)
{
    __shared__ float s_in[8][10][35];   // stride 35 -> conflict-free reads
    __shared__ float s_w[72][32];       // [ic*9+k][oc]

    const int tid = threadIdx.x;
    const int wt = blockIdx.x % 5, ht = blockIdx.x / 5;
    const int w0 = wt * 32, h0 = ht * 8;
    const int oc0 = blockIdx.y * 32;
    const int b = blockIdx.z;

    const int ocq = tid >> 5;           // 0..7 : oc quad
    const int pos = tid & 31;
    const int hl  = pos >> 2;           // 0..7
    const int wb  = (pos & 3) << 3;     // 0,8,16,24

    float acc[4][8];
#pragma unroll
    for (int o = 0; o < 4; o++)
#pragma unroll
        for (int w = 0; w < 8; w++) acc[o][w] = 0.f;

    for (int icc = 0; icc < IC; icc += 8) {
        // stage input 8 ic x 10 rows x 34 cols (with halo, zero padded)
        for (int e = tid; e < 8*10*34; e += 256) {
            int ic = e / 340; int rem = e - ic*340;
            int r = rem / 34; int c = rem - r*34;
            int y = h0 + r - 1, x = w0 + c - 1;
            float vv = 0.f;
            if (y >= 0 && y < HH && x >= 0 && x < WW)
                vv = in[(((size_t)b*IC + icc + ic)*HH + y)*WW + x];
            s_in[ic][r][c] = vv;
        }
        // stage weights 32 oc x (8 ic * 9) — contiguous 72 floats per oc
        for (int e = tid; e < 2304; e += 256) {
            int oc = e / 72; int r = e - oc*72;
            s_w[r][oc] = wgt[((size_t)(oc0 + oc)*IC + icc)*9 + r];
        }
        __syncthreads();

        for (int ic = 0; ic < 8; ic++) {
#pragma unroll
            for (int kh = 0; kh < 3; kh++) {
                float rr[10];
#pragma unroll
                for (int j = 0; j < 10; j++) rr[j] = s_in[ic][hl + kh][wb + j];
#pragma unroll
                for (int kw = 0; kw < 3; kw++) {
                    float wv[4];
#pragma unroll
                    for (int o = 0; o < 4; o++) wv[o] = s_w[ic*9 + kh*3 + kw][ocq*4 + o];
#pragma unroll
                    for (int o = 0; o < 4; o++)
#pragma unroll
                        for (int w = 0; w < 8; w++)
                            acc[o][w] = fmaf(wv[o], rr[w + kw], acc[o][w]);
                }
            }
        }
        __syncthreads();
    }

    const int ho = h0 + hl, wo = w0 + wb;
#pragma unroll
    for (int o = 0; o < 4; o++) {
        int oc = oc0 + ocq*4 + o;
        float sc, sh;
        if (useBN) {
            float s = gam[oc] * rsqrtf(var[oc] + 1e-5f);
            sc = s;
            sh = (bias[oc] - mu[oc]) * s + bet[oc];
        } else {
            sc = 1.f;
            sh = bias[oc];
        }
        size_t base = (((size_t)b*OC + oc)*HH + ho)*WW + wo;
#pragma unroll
        for (int w = 0; w < 8; w++) {
            float vv = acc[o][w] * sc + sh;
            out[base + w] = vv > 0.f ? vv : 0.f;
        }
    }
}

// ---------------------------------------------------------------------------
// 1x1 conv to a single channel + head nonlinearity.
// mode 0: sigmoid -> disparity -> depth.  mode 1: softplus (uncertainty).
// grid: 480 blocks x 256 threads == 122880 pixels exactly.
// ---------------------------------------------------------------------------
__global__ __launch_bounds__(256) void head1x1(
    const float* __restrict__ in, const float* __restrict__ w,
    const float* __restrict__ bias, float* __restrict__ out, int C, int mode)
{
    __shared__ float sw[256];
    if (threadIdx.x < C) sw[threadIdx.x] = w[threadIdx.x];
    __syncthreads();

    int idx = blockIdx.x * 256 + threadIdx.x;
    int b = idx / HW; int p = idx - b*HW;
    const float* base = in + (size_t)b*C*HW + p;
    float acc = bias[0];
#pragma unroll 8
    for (int c = 0; c < C; c++) acc += base[(size_t)c*HW] * sw[c];

    float res;
    if (mode == 0) {
        float disp = 1.f / (1.f + expf(-acc));
        res = 1.f / (0.01f + 9.99f * disp);   // min_disp=1/100, max_disp=1/0.1
    } else {
        res = acc > 20.f ? acc : log1pf(expf(acc));
    }
    out[idx] = res;
}

// ---------------------------------------------------------------------------
// Per-box lower median via exact 32-bit radix select (depth > 0 => uint order
// preserving). One block per (b, n). rank = (k-1)/2.
// ---------------------------------------------------------------------------
__global__ __launch_bounds__(256) void box_median(
    const float* __restrict__ depth, const int* __restrict__ bboxes,
    float* __restrict__ out)
{
    const int bi = blockIdx.x;           // 0..511
    const int b = bi >> 6;
    const int tid = threadIdx.x;
    const int* box = bboxes + (size_t)bi * 4;

    int x1 = max(box[0], 0), y1 = max(box[1], 0);
    int x2 = min(box[2], WW), y2 = min(box[3], HH);
    int wdt = x2 - x1, hgt = y2 - y1;
    if (wdt <= 0 || hgt <= 0) {
        if (tid == 0) out[bi] = 0.f;
        return;
    }
    const int k = wdt * hgt;
    int r = (k - 1) >> 1;

    __shared__ unsigned hist[256];
    const float* dimg = depth + (size_t)b * HW;
    unsigned prefix = 0;

    for (int pass = 0; pass < 4; ++pass) {
        int shift = 24 - 8*pass;
        hist[tid] = 0;
        __syncthreads();
        unsigned pmask = (pass == 0) ? 0u : (0xFFFFFFFFu << (shift + 8));
        for (int e = tid; e < k; e += 256) {
            int y = y1 + e / wdt, x = x1 + e % wdt;
            unsigned bits = __float_as_uint(dimg[y*WW + x]);
            if ((bits & pmask) == prefix)
                atomicAdd(&hist[(bits >> shift) & 0xFF], 1u);
        }
        __syncthreads();
        // all threads scan identically (broadcast reads, uniform result)
        unsigned cum = 0; int bin = -1;
        for (int i = 0; i < 256; i++) {
            unsigned h = hist[i];
            if (bin < 0 && r < (int)(cum + h)) { bin = i; r -= (int)cum; }
            cum += h;
        }
        prefix |= ((unsigned)bin) << shift;
        __syncthreads();   // protect hist before next pass reset
    }
    if (tid == 0) out[bi] = __uint_as_float(prefix);
}

// ---------------------------------------------------------------------------
extern "C" void kernel_launch(void* const* d_in, const int* in_sizes, int n_in,
                              void* d_out, int out_size)
{
    const float* features = (const float*)d_in[0];
    const int*   bboxes   = (const int*)  d_in[1];
    const float* w1  = (const float*)d_in[2];
    const float* b1  = (const float*)d_in[3];
    const float* g1  = (const float*)d_in[4];
    const float* be1 = (const float*)d_in[5];
    const float* m1  = (const float*)d_in[6];
    const float* v1  = (const float*)d_in[7];
    const float* w2  = (const float*)d_in[8];
    const float* b2  = (const float*)d_in[9];
    const float* g2  = (const float*)d_in[10];
    const float* be2 = (const float*)d_in[11];
    const float* m2  = (const float*)d_in[12];
    const float* v2  = (const float*)d_in[13];
    const float* w3  = (const float*)d_in[14];
    const float* b3  = (const float*)d_in[15];
    const float* uw1 = (const float*)d_in[16];
    const float* ub1 = (const float*)d_in[17];
    const float* uw2 = (const float*)d_in[18];
    const float* ub2 = (const float*)d_in[19];

    float* out = (float*)d_out;

    float *h1, *h2, *u1;
    cudaGetSymbolAddress((void**)&h1, g_h1);
    cudaGetSymbolAddress((void**)&h2, g_h2);
    cudaGetSymbolAddress((void**)&u1, g_u1);

    dim3 cgrid(60, 8, 8);    // 5 Wtiles * 12 Htiles, 8 oc-tiles, 8 batch
    dim3 ugrid(60, 4, 8);

    // depth head
    conv3x3_bn_relu<<<cgrid, 256>>>(features, w1, b1, g1, be1, m1, v1, h1, 256, 256, 1);
    conv3x3_bn_relu<<<cgrid, 256>>>(h1,       w2, b2, g2, be2, m2, v2, h2, 256, 256, 1);
    head1x1<<<480, 256>>>(h2, w3, b3, out, 256, 0);                 // depth -> out[0:122880)

    // uncertainty head
    conv3x3_bn_relu<<<ugrid, 256>>>(features, uw1, ub1, nullptr, nullptr, nullptr, nullptr,
                                    u1, 256, 128, 0);
    head1x1<<<480, 256>>>(u1, uw2, ub2, out + 122880, 128, 1);      // unc -> out[122880:245760)

    // per-box medians from depth
    box_median<<<512, 256>>>(out, bboxes, out + 245760);            // obj -> out[245760:246272)
}